// round 2
// baseline (speedup 1.0000x reference)
#include <cuda_runtime.h>
#include <math.h>

// Problem shape (fixed by reference setup_inputs)
#define BB 8
#define DD 64
#define HH 256
#define WW 512
#define HW (HH * WW)          // 131072
#define PIXELS (BB * HW)      // 1048576
#define NBLOCKS 1024          // PIXELS / 4 / 256

#define E2     7.389056098930650f   // e^2
#define INV_E2 0.135335283236613f   // e^-2

// Allocation-free scratch
__device__ float        g_partial[NBLOCKS];
__device__ int          g_pcnt[NBLOCKS];
__device__ unsigned int g_done;      // zero-init; reset by last block each replay

// One fused kernel:
//   entropy = log(sum_d exp(x_d)) - (sum_d w_d*x_d)/(sum_d w_d)
// with w_d = exp(-|gt - 2d|) computed by a geometric recurrence
// (scaled by exp(63), which cancels in the ratio).
__global__ void __launch_bounds__(256)
sce_fused_kernel(const float* __restrict__ sim, const float* __restrict__ gt,
                 float* __restrict__ out) {
    const int tid = blockIdx.x * blockDim.x + threadIdx.x;
    const int p   = tid * 4;                       // base pixel index
    const int b   = p / HW;
    const int rem = p - b * HW;

    const float4* simv = (const float4*)(sim + (size_t)b * DD * HW + rem);

    const float4 g = *(const float4*)(gt + p);
    float gtv[4] = {g.x, g.y, g.z, g.w};

    float se[4], spt[4], sptx[4], v[4], ms[4];
    #pragma unroll
    for (int j = 0; j < 4; ++j) {
        se[j]  = 0.f;
        spt[j] = 0.f;
        sptx[j] = 0.f;
        // scaled initial Laplace weight: exp(63 - gt); 0 for gt=inf
        v[j] = __expf(63.0f - gtv[j]);
        // one-time crossing multiplier: exp(2*gt - 4*floor(gt/2) - 2)
        ms[j] = __expf(2.0f * gtv[j] - 4.0f * floorf(gtv[j] * 0.5f) - 2.0f);
    }

    float d2 = 0.0f;   // 2*d, carried
    #pragma unroll 8
    for (int d = 0; d < DD; ++d) {
        const float4 x = simv[(size_t)d * (HW / 4)];
        const float xs[4] = {x.x, x.y, x.z, x.w};
        #pragma unroll
        for (int j = 0; j < 4; ++j) {
            const float xx = xs[j];
            se[j]   += __expf(xx);
            spt[j]  += v[j];
            sptx[j] += v[j] * xx;
            // advance Laplace weight: e^2 below the peak, e^-2 above,
            // special one-shot multiplier at the crossing step
            const float m = (d2 + 2.0f <= gtv[j]) ? E2
                          : ((d2 >= gtv[j]) ? INV_E2 : ms[j]);
            v[j] *= m;
        }
        d2 += 2.0f;
    }

    float local = 0.f;
    int   cnt   = 0;
    #pragma unroll
    for (int j = 0; j < 4; ++j) {
        if (isfinite(gtv[j])) {
            local += __logf(se[j]) - __fdividef(sptx[j], spt[j]);
            cnt   += 1;
        }
    }

    // Block reduce (8 warps)
    #pragma unroll
    for (int o = 16; o > 0; o >>= 1) {
        local += __shfl_down_sync(0xffffffffu, local, o);
        cnt   += __shfl_down_sync(0xffffffffu, cnt, o);
    }
    __shared__ float ssum[8];
    __shared__ int   scnt[8];
    __shared__ bool  isLast;
    const int lane = threadIdx.x & 31;
    const int wid  = threadIdx.x >> 5;
    if (lane == 0) { ssum[wid] = local; scnt[wid] = cnt; }
    __syncthreads();
    if (wid == 0) {
        local = (lane < 8) ? ssum[lane] : 0.f;
        cnt   = (lane < 8) ? scnt[lane] : 0;
        #pragma unroll
        for (int o = 4; o > 0; o >>= 1) {
            local += __shfl_down_sync(0xffffffffu, local, o);
            cnt   += __shfl_down_sync(0xffffffffu, cnt, o);
        }
        if (lane == 0) {
            g_partial[blockIdx.x] = local;
            g_pcnt[blockIdx.x]    = cnt;
            __threadfence();
            unsigned int prev = atomicAdd(&g_done, 1u);
            isLast = (prev == (unsigned int)(gridDim.x - 1));
        }
    }
    __syncthreads();

    // Last block to finish reduces all partials (deterministic order)
    if (isLast) {
        __threadfence();
        const volatile float* vp = g_partial;
        const volatile int*   vc = g_pcnt;
        float s = 0.f;
        int   c = 0;
        #pragma unroll
        for (int k = 0; k < NBLOCKS / 256; ++k) {
            s += vp[threadIdx.x + k * 256];
            c += vc[threadIdx.x + k * 256];
        }
        #pragma unroll
        for (int o = 16; o > 0; o >>= 1) {
            s += __shfl_down_sync(0xffffffffu, s, o);
            c += __shfl_down_sync(0xffffffffu, c, o);
        }
        if (lane == 0) { ssum[wid] = s; scnt[wid] = c; }
        __syncthreads();
        if (wid == 0) {
            s = (lane < 8) ? ssum[lane] : 0.f;
            c = (lane < 8) ? scnt[lane] : 0;
            #pragma unroll
            for (int o = 4; o > 0; o >>= 1) {
                s += __shfl_down_sync(0xffffffffu, s, o);
                c += __shfl_down_sync(0xffffffffu, c, o);
            }
            if (lane == 0) {
                out[0] = s / (float)c;
                g_done = 0;   // reset for next graph replay
            }
        }
    }
}

extern "C" void kernel_launch(void* const* d_in, const int* in_sizes, int n_in,
                              void* d_out, int out_size) {
    const float* sim = (const float*)d_in[0];
    const float* gt  = (const float*)d_in[1];
    float* out       = (float*)d_out;

    sce_fused_kernel<<<NBLOCKS, 256>>>(sim, gt, out);
}

// round 3
// speedup vs baseline: 1.5831x; 1.5831x over previous
#include <cuda_runtime.h>
#include <math.h>

// Problem shape (fixed by reference setup_inputs)
#define BB 8
#define DD 64
#define HW (256 * 512)        // 131072
#define PIXELS (BB * HW)      // 1048576
#define NBLOCKS 1024          // PIXELS / 4 / 256

#define E2      7.3890560989306495f   // e^2
#define INV_E2  0.1353352832366127f   // e^-2
#define E_P63   2.2937831594696098e27f  // e^63
#define E_M63   4.3596100000630809e-28f // e^-63

// Allocation-free scratch
__device__ float        g_partial[NBLOCKS];
__device__ int          g_pcnt[NBLOCKS];
__device__ unsigned int g_done;      // zero-init; reset by last block each replay

// entropy = log(sum_d exp(x_d)) - (sum_d w_d*x_d)/(sum_d w_d)
// w_d = e^{-|gt-2d|} = (2d<=gt) ? t_lo[d]*c1 : t_hi[d]*c2
//   t_lo[d]=e^{2d-63} (uniform, carried), c1=e^{63-gt} (per-pixel, hoisted)
//   t_hi[d]=e^{63-2d},                    c2=e^{gt-63}
__global__ void __launch_bounds__(256)
sce_fused_kernel(const float* __restrict__ sim, const float* __restrict__ gt,
                 float* __restrict__ out) {
    const int tid = blockIdx.x * blockDim.x + threadIdx.x;
    const int p   = tid * 4;
    const int b   = p / HW;
    const int rem = p - b * HW;

    const float4* simv = (const float4*)(sim + (size_t)b * DD * HW + rem);

    const float4 g = *(const float4*)(gt + p);
    const float gtv[4] = {g.x, g.y, g.z, g.w};

    float se[4], spt[4], sptx[4], c1[4], c2[4];
    #pragma unroll
    for (int j = 0; j < 4; ++j) {
        se[j] = 0.f; spt[j] = 0.f; sptx[j] = 0.f;
        c1[j] = __expf(63.0f - gtv[j]);   // 0 when gt = inf
        c2[j] = __expf(gtv[j] - 63.0f);
    }

    float t_lo = E_M63;   // e^{2d-63}, uniform across warp
    float t_hi = E_P63;   // e^{63-2d}
    float dd   = 0.0f;    // 2*d

    #pragma unroll 8
    for (int d = 0; d < DD; ++d) {
        const float4 x = simv[(size_t)d * (HW / 4)];
        const float xs[4] = {x.x, x.y, x.z, x.w};
        #pragma unroll
        for (int j = 0; j < 4; ++j) {
            const float xx = xs[j];
            se[j] += __expf(xx);
            const bool lo = (dd <= gtv[j]);
            const float t = lo ? t_lo : t_hi;
            const float c = lo ? c1[j] : c2[j];
            const float w = t * c;
            spt[j]  += w;
            sptx[j] += w * xx;
        }
        t_lo *= E2;
        t_hi *= INV_E2;
        dd   += 2.0f;
    }

    float local = 0.f;
    int   cnt   = 0;
    #pragma unroll
    for (int j = 0; j < 4; ++j) {
        if (isfinite(gtv[j])) {
            local += __logf(se[j]) - __fdividef(sptx[j], spt[j]);
            cnt   += 1;
        }
    }

    // Block reduce (8 warps)
    #pragma unroll
    for (int o = 16; o > 0; o >>= 1) {
        local += __shfl_down_sync(0xffffffffu, local, o);
        cnt   += __shfl_down_sync(0xffffffffu, cnt, o);
    }
    __shared__ float ssum[8];
    __shared__ int   scnt[8];
    __shared__ bool  isLast;
    const int lane = threadIdx.x & 31;
    const int wid  = threadIdx.x >> 5;
    if (lane == 0) { ssum[wid] = local; scnt[wid] = cnt; }
    __syncthreads();
    if (wid == 0) {
        local = (lane < 8) ? ssum[lane] : 0.f;
        cnt   = (lane < 8) ? scnt[lane] : 0;
        #pragma unroll
        for (int o = 4; o > 0; o >>= 1) {
            local += __shfl_down_sync(0xffffffffu, local, o);
            cnt   += __shfl_down_sync(0xffffffffu, cnt, o);
        }
        if (lane == 0) {
            g_partial[blockIdx.x] = local;
            g_pcnt[blockIdx.x]    = cnt;
            __threadfence();
            unsigned int prev = atomicAdd(&g_done, 1u);
            isLast = (prev == (unsigned int)(gridDim.x - 1));
        }
    }
    __syncthreads();

    // Last block reduces all partials
    if (isLast) {
        __threadfence();
        const volatile float* vp = g_partial;
        const volatile int*   vc = g_pcnt;
        float s = 0.f;
        int   c = 0;
        #pragma unroll
        for (int k = 0; k < NBLOCKS / 256; ++k) {
            s += vp[threadIdx.x + k * 256];
            c += vc[threadIdx.x + k * 256];
        }
        #pragma unroll
        for (int o = 16; o > 0; o >>= 1) {
            s += __shfl_down_sync(0xffffffffu, s, o);
            c += __shfl_down_sync(0xffffffffu, c, o);
        }
        if (lane == 0) { ssum[wid] = s; scnt[wid] = c; }
        __syncthreads();
        if (wid == 0) {
            s = (lane < 8) ? ssum[lane] : 0.f;
            c = (lane < 8) ? scnt[lane] : 0;
            #pragma unroll
            for (int o = 4; o > 0; o >>= 1) {
                s += __shfl_down_sync(0xffffffffu, s, o);
                c += __shfl_down_sync(0xffffffffu, c, o);
            }
            if (lane == 0) {
                out[0] = s / (float)c;
                g_done = 0;   // reset for next graph replay
            }
        }
    }
}

extern "C" void kernel_launch(void* const* d_in, const int* in_sizes, int n_in,
                              void* d_out, int out_size) {
    const float* sim = (const float*)d_in[0];
    const float* gt  = (const float*)d_in[1];
    float* out       = (float*)d_out;

    sce_fused_kernel<<<NBLOCKS, 256>>>(sim, gt, out);
}